// round 14
// baseline (speedup 1.0000x reference)
#include <cuda_runtime.h>
#include <cuda_fp16.h>

// Grid4D quadrilinear sample — overlapped producer/consumer on two streams:
//  stream 0: binning chain, then persistent gather (sorted ascending by u-stripe,
//            per-point gated on slabDone[u]) — trails the transpose frontier,
//            so gridT reads hit L2.
//  stream B: u-major transpose grid [R,X,Y,U,V] fp32 -> gridT [X,Y,U,V,R] fp16,
//            bumping slabDone[u] per 256-cell chunk.

#define RR 8
#define XX 9
#define YY 9
#define UU 512
#define VV 512
#define NS (XX * YY * UU * VV)     // 21,233,664 spatial cells
#define STR_R (NS)
#define STR_Y (UU * VV)

#define NBINS 65536
#define SCAN_BLOCKS 64
#define NCAP (1 << 20)
#define GATHER_BLOCKS 444          // 3 per SM; transpose fills the rest
#define CHUNK 256
#define N_SLABS UU                 // 512 u-slabs
#define T_CHUNKS_PER_SLAB 162      // 81*512/256 cells per slab / 256
#define NT_BLOCKS (N_SLABS * T_CHUNKS_PER_SLAB)

__device__ uint4 g_gridT[(size_t)NS];            // ~340 MB fp16 transposed grid
__device__ unsigned int g_binCnt[NBINS];
__device__ unsigned int g_binCursor[NBINS];
__device__ unsigned int g_blkSum[SCAN_BLOCKS];
__device__ unsigned int g_blkOff[SCAN_BLOCKS];
__device__ float4 g_pts[NCAP];                   // sorted coords (16 MB)
__device__ unsigned int g_oidx[NCAP];            // original index (4 MB)
__device__ unsigned int g_slabDone[N_SLABS];
__device__ unsigned int g_ticket;

__device__ __forceinline__ unsigned int h2_to_u32(__half2 v) {
    return *reinterpret_cast<unsigned int*>(&v);
}
__device__ __forceinline__ __half2 u32_to_h2(unsigned int v) {
    return *reinterpret_cast<__half2*>(&v);
}

// ---------------- transpose (u-major, slab progress counters) ----------------
__global__ void __launch_bounds__(256)
transpose_kernel(const float* __restrict__ grid) {
    int bid = blockIdx.x;                       // [0, NT_BLOCKS)
    int u = bid / T_CHUNKS_PER_SLAB;
    int cell = (bid % T_CHUNKS_PER_SLAB) * 256 + threadIdx.x;  // [0, 41472)
    int xy = cell >> 9;                         // (x*9+y) in [0,81)
    int v  = cell & 511;
    int s  = xy * STR_Y + u * VV + v;
    uint4 packed;
    unsigned int* pu = &packed.x;
#pragma unroll
    for (int p = 0; p < 4; p++) {
        float a = __ldg(grid + (2 * p + 0) * STR_R + s);
        float b = __ldg(grid + (2 * p + 1) * STR_R + s);
        pu[p] = h2_to_u32(__floats2half2_rn(a, b));
    }
    g_gridT[s] = packed;
    __threadfence();
    __syncthreads();
    if (threadIdx.x == 0) atomicAdd(&g_slabDone[u], 1u);
}

// ---------------- shared coordinate math ----------------
__device__ __forceinline__ void prep_dim(float c, float mn, float mx, int S,
                                         int& c0, int& dd, float& w0, float& w1) {
    float ind = (c - mn) / (mx - mn) * 2.0f - 1.0f;
    float pos = (ind + 1.0f) * 0.5f * (float)(S - 1);
    float fl = floorf(pos);
    int i0 = (int)fl;
    float f = pos - fl;
    w0 = 1.0f - f;
    w1 = f;
    if (i0 < 0 || i0 >= S) w0 = 0.0f;        // zero-padding semantics
    int i1 = i0 + 1;
    if (i1 < 0 || i1 >= S) w1 = 0.0f;
    int cc0 = min(max(i0, 0), S - 1);
    int cc1 = min(max(i1, 0), S - 1);
    c0 = cc0;
    dd = cc1 - cc0;                           // 0 or 1
}

__device__ __forceinline__ int base_idx(float c, float mn, float mx, int S) {
    float ind = (c - mn) / (mx - mn) * 2.0f - 1.0f;
    float pos = (ind + 1.0f) * 0.5f * (float)(S - 1);
    int i0 = (int)floorf(pos);
    return min(max(i0, 0), S - 1);
}

// key = [u_hi3][v_hi3][x:3][y:3][u_mid2,v_mid2 interleaved:4]  (16 bits)
// u-stripes ascend so gather trails the u-major transpose frontier.
__device__ __forceinline__ int compute_bin(float4 c, const float* mn4, const float* mx4) {
    int x0 = min(base_idx(c.x, mn4[0], mx4[0], XX), 7);
    int y0 = min(base_idx(c.y, mn4[1], mx4[1], YY), 7);
    int u0 = base_idx(c.z, mn4[2], mx4[2], UU);
    int v0 = base_idx(c.w, mn4[3], mx4[3], VV);
    int uh = u0 >> 6, vh = v0 >> 6;
    int um = (u0 >> 4) & 3, vm = (v0 >> 4) & 3;
    int mid = (um & 1) | ((vm & 1) << 1) | ((um >> 1) << 2) | ((vm >> 1) << 3);
    return (((((((uh << 3) | vh) << 3) | x0) << 3) | y0) << 4) | mid;
}

// ---------------- binning ----------------
__global__ void __launch_bounds__(1024)
zero_kernel() {
    int b = blockIdx.x * blockDim.x + threadIdx.x;
    if (b < NBINS) g_binCnt[b] = 0;
    if (b < N_SLABS) g_slabDone[b] = 0;
    if (b == 0) g_ticket = 0;
}

__global__ void __launch_bounds__(256)
hist_kernel(const float4* __restrict__ xyuv,
            const float* __restrict__ mn4, const float* __restrict__ mx4, int n) {
    int i = blockIdx.x * blockDim.x + threadIdx.x;
    if (i < n) atomicAdd(&g_binCnt[compute_bin(xyuv[i], mn4, mx4)], 1u);
}

__global__ void __launch_bounds__(1024)
scan_local_kernel() {
    __shared__ unsigned int s[1024];
    int t = threadIdx.x;
    int b = blockIdx.x * 1024 + t;
    unsigned int v = g_binCnt[b];
    s[t] = v;
    __syncthreads();
    for (int off = 1; off < 1024; off <<= 1) {
        unsigned int x = (t >= off) ? s[t - off] : 0u;
        __syncthreads();
        s[t] += x;
        __syncthreads();
    }
    g_binCursor[b] = s[t] - v;   // exclusive
    if (t == 1023) g_blkSum[blockIdx.x] = s[t];
}

__global__ void __launch_bounds__(SCAN_BLOCKS)
scan_top_kernel() {
    __shared__ unsigned int s[SCAN_BLOCKS];
    int t = threadIdx.x;
    unsigned int v = g_blkSum[t];
    s[t] = v;
    __syncthreads();
    for (int off = 1; off < SCAN_BLOCKS; off <<= 1) {
        unsigned int x = (t >= off) ? s[t - off] : 0u;
        __syncthreads();
        s[t] += x;
        __syncthreads();
    }
    g_blkOff[t] = s[t] - v;      // exclusive
}

__global__ void __launch_bounds__(1024)
scan_add_kernel() {
    int b = blockIdx.x * 1024 + threadIdx.x;
    g_binCursor[b] += g_blkOff[blockIdx.x];
}

__global__ void __launch_bounds__(256)
scatter_kernel(const float4* __restrict__ xyuv,
               const float* __restrict__ mn4, const float* __restrict__ mx4, int n) {
    int i = blockIdx.x * blockDim.x + threadIdx.x;
    if (i >= n) return;
    float4 c = xyuv[i];
    int bin = compute_bin(c, mn4, mx4);
    unsigned int pos = atomicAdd(&g_binCursor[bin], 1u);
    g_pts[pos] = c;
    g_oidx[pos] = (unsigned int)i;
}

// ---------------- persistent gather, gated on slabDone ----------------
__global__ void __launch_bounds__(256)
gather_kernel(const float* __restrict__ mn4,
              const float* __restrict__ mx4,
              float* __restrict__ out, int n) {
    __shared__ unsigned int s_chunk;
    int nChunks = (n + CHUNK - 1) / CHUNK;

    for (;;) {
        __syncthreads();
        if (threadIdx.x == 0) s_chunk = atomicAdd(&g_ticket, 1u);
        __syncthreads();
        unsigned int chunk = s_chunk;
        if (chunk >= (unsigned int)nChunks) return;

        int t = (int)chunk * CHUNK + threadIdx.x;
        if (t < n) {
            float4 c = g_pts[t];

            int x0, y0, u0, v0, dx, dy, du, dv;
            float wx0, wx1, wy0, wy1, wu0, wu1, wv0, wv1;
            prep_dim(c.x, mn4[0], mx4[0], XX, x0, dx, wx0, wx1);
            prep_dim(c.y, mn4[1], mx4[1], YY, y0, dy, wy0, wy1);
            prep_dim(c.z, mn4[2], mx4[2], UU, u0, du, wu0, wu1);
            prep_dim(c.w, mn4[3], mx4[3], VV, v0, dv, wv0, wv1);

            // wait until the two needed u-slabs are transposed
            int u1 = u0 + du;
            volatile unsigned int* sd = g_slabDone;
            while (sd[u0] < T_CHUNKS_PER_SLAB || sd[u1] < T_CHUNKS_PER_SLAB)
                __nanosleep(128);
            __threadfence();   // order slabDone observation before data loads

            int sidx[8];
            float w[8];
#pragma unroll
            for (int k = 0; k < 8; k++) {
                int xa = (k >> 2) & 1;
                int ya = (k >> 1) & 1;
                int ua = k & 1;
                int xi = x0 + (xa ? dx : 0);
                int yi = y0 + (ya ? dy : 0);
                int ui = u0 + (ua ? du : 0);
                sidx[k] = ((xi * YY + yi) * UU + ui) * VV + v0;
                w[k] = (xa ? wx1 : wx0) * (ya ? wy1 : wy0) * (ua ? wu1 : wu0);
            }

            float acc[RR];
#pragma unroll
            for (int r = 0; r < RR; r++) acc[r] = 0.0f;

#pragma unroll 2
            for (int k = 0; k < 8; k++) {
                int s0 = sidx[k];
                uint4 A = g_gridT[s0];
                uint4 B = g_gridT[s0 + dv];
                float wa = w[k] * wv0;
                float wb = w[k] * wv1;
                const unsigned int* au = &A.x;
                const unsigned int* bu = &B.x;
#pragma unroll
                for (int p = 0; p < 4; p++) {
                    float2 fa = __half22float2(u32_to_h2(au[p]));
                    float2 fb = __half22float2(u32_to_h2(bu[p]));
                    acc[2 * p + 0] = fmaf(wa, fa.x, fmaf(wb, fb.x, acc[2 * p + 0]));
                    acc[2 * p + 1] = fmaf(wa, fa.y, fmaf(wb, fb.y, acc[2 * p + 1]));
                }
            }

            unsigned int oi = g_oidx[t];
            float4* o4 = reinterpret_cast<float4*>(out + (size_t)oi * RR);
            o4[0] = make_float4(acc[0], acc[1], acc[2], acc[3]);
            o4[1] = make_float4(acc[4], acc[5], acc[6], acc[7]);
        }
    }
}

extern "C" void kernel_launch(void* const* d_in, const int* in_sizes, int n_in,
                              void* d_out, int out_size) {
    const float4* xyuv = (const float4*)d_in[0];
    const float* grid  = (const float*)d_in[1];
    const float* mn4   = (const float*)d_in[2];
    const float* mx4   = (const float*)d_in[3];
    float* out = (float*)d_out;

    int n = in_sizes[0] / 4;  // 1,048,576 points
    if (n > NCAP) n = NCAP;

    static cudaStream_t sB = nullptr;
    static cudaEvent_t evFork = nullptr, evJoin = nullptr;
    if (!sB) {
        cudaStreamCreateWithFlags(&sB, cudaStreamNonBlocking);
        cudaEventCreateWithFlags(&evFork, cudaEventDisableTiming);
        cudaEventCreateWithFlags(&evJoin, cudaEventDisableTiming);
    }

    int pBlocks = (n + 255) / 256;

    // counters (incl. slabDone) must be zeroed before the transpose starts
    zero_kernel<<<NBINS / 1024, 1024>>>();

    // Fork: transpose runs on side stream, concurrent with binning + gather.
    cudaEventRecord(evFork, 0);
    cudaStreamWaitEvent(sB, evFork, 0);
    transpose_kernel<<<NT_BLOCKS, 256, 0, sB>>>(grid);

    // Stream 0: binning chain, then the gated gather (polls slabDone).
    hist_kernel<<<pBlocks, 256>>>(xyuv, mn4, mx4, n);
    scan_local_kernel<<<SCAN_BLOCKS, 1024>>>();
    scan_top_kernel<<<1, SCAN_BLOCKS>>>();
    scan_add_kernel<<<SCAN_BLOCKS, 1024>>>();
    scatter_kernel<<<pBlocks, 256>>>(xyuv, mn4, mx4, n);
    gather_kernel<<<GATHER_BLOCKS, 256>>>(mn4, mx4, out, n);

    // Join: make stream 0 wait for transpose completion at the end.
    cudaEventRecord(evJoin, sB);
    cudaStreamWaitEvent(0, evJoin, 0);
}

// round 15
// speedup vs baseline: 1.0068x; 1.0068x over previous
#include <cuda_runtime.h>
#include <cuda_fp16.h>

// Grid4D quadrilinear sample — stripe-pipelined producer/consumer:
//  stream A: 8 u-stripe transposes (grid fp32 -> gridT fp16), event after each
//  stream 0: binning chain (sort by [stripe][v_hi][x][y][mid]), then 8 gather
//            kernels, each event-gated on its transpose stripe -> gridT reads
//            hit L2 (42.5MB stripe just written). No spin-waits.

#define RR 8
#define XX 9
#define YY 9
#define UU 512
#define VV 512
#define NS (XX * YY * UU * VV)     // 21,233,664 spatial cells
#define STR_R (NS)
#define STR_Y (UU * VV)

#define NBINS 65536
#define SCAN_BLOCKS 64
#define NCAP (1 << 20)
#define N_STRIPES 8
#define U_PER_STRIPE 64
#define T_STRIPE_CELLS (XX * YY * U_PER_STRIPE * VV)   // 2,654,208
#define T_STRIPE_BLOCKS (T_STRIPE_CELLS / 256)         // 10,368
#define GATHER_STRIPE_BLOCKS 1024

__device__ uint4 g_gridT[(size_t)NS];            // ~340 MB fp16 transposed grid
__device__ unsigned int g_binCnt[NBINS];
__device__ unsigned int g_binCursor[NBINS];
__device__ unsigned int g_blkSum[SCAN_BLOCKS];
__device__ unsigned int g_blkOff[SCAN_BLOCKS];
__device__ unsigned int g_stripeStart[N_STRIPES + 1];
__device__ float4 g_pts[NCAP];                   // sorted coords (16 MB)
__device__ unsigned int g_oidx[NCAP];            // original index (4 MB)

__device__ __forceinline__ unsigned int h2_to_u32(__half2 v) {
    return *reinterpret_cast<unsigned int*>(&v);
}
__device__ __forceinline__ __half2 u32_to_h2(unsigned int v) {
    return *reinterpret_cast<__half2*>(&v);
}

// ---------------- transpose of one u-stripe ----------------
__global__ void __launch_bounds__(256)
transpose_stripe_kernel(const float* __restrict__ grid, int stripe) {
    int id = blockIdx.x * 256 + threadIdx.x;     // [0, T_STRIPE_CELLS)
    int v = id & 511;
    int rest = id >> 9;                          // xy*64 + ul
    int ul = rest & 63;
    int xy = rest >> 6;                          // [0, 81)
    int s = xy * STR_Y + (stripe * U_PER_STRIPE + ul) * VV + v;
    uint4 packed;
    unsigned int* pu = &packed.x;
#pragma unroll
    for (int p = 0; p < 4; p++) {
        float a = __ldg(grid + (2 * p + 0) * STR_R + s);
        float b = __ldg(grid + (2 * p + 1) * STR_R + s);
        pu[p] = h2_to_u32(__floats2half2_rn(a, b));
    }
    g_gridT[s] = packed;
}

// ---------------- shared coordinate math ----------------
__device__ __forceinline__ void prep_dim(float c, float mn, float mx, int S,
                                         int& c0, int& dd, float& w0, float& w1) {
    float ind = (c - mn) / (mx - mn) * 2.0f - 1.0f;
    float pos = (ind + 1.0f) * 0.5f * (float)(S - 1);
    float fl = floorf(pos);
    int i0 = (int)fl;
    float f = pos - fl;
    w0 = 1.0f - f;
    w1 = f;
    if (i0 < 0 || i0 >= S) w0 = 0.0f;        // zero-padding semantics
    int i1 = i0 + 1;
    if (i1 < 0 || i1 >= S) w1 = 0.0f;
    int cc0 = min(max(i0, 0), S - 1);
    int cc1 = min(max(i1, 0), S - 1);
    c0 = cc0;
    dd = cc1 - cc0;                           // 0 or 1
}

__device__ __forceinline__ int base_idx(float c, float mn, float mx, int S) {
    float ind = (c - mn) / (mx - mn) * 2.0f - 1.0f;
    float pos = (ind + 1.0f) * 0.5f * (float)(S - 1);
    int i0 = (int)floorf(pos);
    return min(max(i0, 0), S - 1);
}

// key = [stripe:3][v_hi:3][x:3][y:3][morton(u_mid,v_mid):4]
// stripe = highest u-corner >> 6, so gather-stripe s only needs u-slabs <= end of stripe s.
__device__ __forceinline__ int compute_bin(float4 c, const float* mn4, const float* mx4) {
    int x0 = min(base_idx(c.x, mn4[0], mx4[0], XX), 7);
    int y0 = min(base_idx(c.y, mn4[1], mx4[1], YY), 7);
    int u0 = base_idx(c.z, mn4[2], mx4[2], UU);
    int v0 = base_idx(c.w, mn4[3], mx4[3], VV);
    int stripe = min(u0 + 1, UU - 1) >> 6;
    int vh = v0 >> 6;
    int um = (u0 >> 4) & 3, vm = (v0 >> 4) & 3;
    int mid = (um & 1) | ((vm & 1) << 1) | ((um >> 1) << 2) | ((vm >> 1) << 3);
    return (((((((stripe << 3) | vh) << 3) | x0) << 3) | y0) << 4) | mid;
}

// ---------------- binning ----------------
__global__ void __launch_bounds__(1024)
zero_kernel() {
    int b = blockIdx.x * blockDim.x + threadIdx.x;
    if (b < NBINS) g_binCnt[b] = 0;
}

__global__ void __launch_bounds__(256)
hist_kernel(const float4* __restrict__ xyuv,
            const float* __restrict__ mn4, const float* __restrict__ mx4, int n) {
    int i = blockIdx.x * blockDim.x + threadIdx.x;
    if (i < n) atomicAdd(&g_binCnt[compute_bin(xyuv[i], mn4, mx4)], 1u);
}

__global__ void __launch_bounds__(1024)
scan_local_kernel() {
    __shared__ unsigned int s[1024];
    int t = threadIdx.x;
    int b = blockIdx.x * 1024 + t;
    unsigned int v = g_binCnt[b];
    s[t] = v;
    __syncthreads();
    for (int off = 1; off < 1024; off <<= 1) {
        unsigned int x = (t >= off) ? s[t - off] : 0u;
        __syncthreads();
        s[t] += x;
        __syncthreads();
    }
    g_binCursor[b] = s[t] - v;   // exclusive (local)
    if (t == 1023) g_blkSum[blockIdx.x] = s[t];
}

__global__ void __launch_bounds__(SCAN_BLOCKS)
scan_top_kernel(int n) {
    __shared__ unsigned int s[SCAN_BLOCKS];
    int t = threadIdx.x;
    unsigned int v = g_blkSum[t];
    s[t] = v;
    __syncthreads();
    for (int off = 1; off < SCAN_BLOCKS; off <<= 1) {
        unsigned int x = (t >= off) ? s[t - off] : 0u;
        __syncthreads();
        s[t] += x;
        __syncthreads();
    }
    g_blkOff[t] = s[t] - v;      // exclusive
    if (t == 0) g_stripeStart[N_STRIPES] = (unsigned int)n;
}

__global__ void __launch_bounds__(1024)
scan_add_kernel() {
    int b = blockIdx.x * 1024 + threadIdx.x;
    unsigned int val = g_binCursor[b] + g_blkOff[blockIdx.x];
    g_binCursor[b] = val;
    // stripe boundaries: bins are [stripe:3][13 lower bits]
    if ((b & 8191) == 0) g_stripeStart[b >> 13] = val;
}

__global__ void __launch_bounds__(256)
scatter_kernel(const float4* __restrict__ xyuv,
               const float* __restrict__ mn4, const float* __restrict__ mx4, int n) {
    int i = blockIdx.x * blockDim.x + threadIdx.x;
    if (i >= n) return;
    float4 c = xyuv[i];
    int bin = compute_bin(c, mn4, mx4);
    unsigned int pos = atomicAdd(&g_binCursor[bin], 1u);
    g_pts[pos] = c;
    g_oidx[pos] = (unsigned int)i;
}

// ---------------- per-stripe gather (grid-stride over the stripe's range) ----------------
__global__ void __launch_bounds__(256)
gather_stripe_kernel(const float* __restrict__ mn4,
                     const float* __restrict__ mx4,
                     float* __restrict__ out, int stripe) {
    unsigned int start = g_stripeStart[stripe];
    unsigned int end   = g_stripeStart[stripe + 1];

    for (unsigned int t = start + blockIdx.x * blockDim.x + threadIdx.x;
         t < end; t += (unsigned int)gridDim.x * blockDim.x) {
        float4 c = g_pts[t];

        int x0, y0, u0, v0, dx, dy, du, dv;
        float wx0, wx1, wy0, wy1, wu0, wu1, wv0, wv1;
        prep_dim(c.x, mn4[0], mx4[0], XX, x0, dx, wx0, wx1);
        prep_dim(c.y, mn4[1], mx4[1], YY, y0, dy, wy0, wy1);
        prep_dim(c.z, mn4[2], mx4[2], UU, u0, du, wu0, wu1);
        prep_dim(c.w, mn4[3], mx4[3], VV, v0, dv, wv0, wv1);

        int sidx[8];
        float w[8];
#pragma unroll
        for (int k = 0; k < 8; k++) {
            int xa = (k >> 2) & 1;
            int ya = (k >> 1) & 1;
            int ua = k & 1;
            int xi = x0 + (xa ? dx : 0);
            int yi = y0 + (ya ? dy : 0);
            int ui = u0 + (ua ? du : 0);
            sidx[k] = ((xi * YY + yi) * UU + ui) * VV + v0;
            w[k] = (xa ? wx1 : wx0) * (ya ? wy1 : wy0) * (ua ? wu1 : wu0);
        }

        float acc[RR];
#pragma unroll
        for (int r = 0; r < RR; r++) acc[r] = 0.0f;

#pragma unroll 2
        for (int k = 0; k < 8; k++) {
            int s0 = sidx[k];
            uint4 A = g_gridT[s0];
            uint4 B = g_gridT[s0 + dv];
            float wa = w[k] * wv0;
            float wb = w[k] * wv1;
            const unsigned int* au = &A.x;
            const unsigned int* bu = &B.x;
#pragma unroll
            for (int p = 0; p < 4; p++) {
                float2 fa = __half22float2(u32_to_h2(au[p]));
                float2 fb = __half22float2(u32_to_h2(bu[p]));
                acc[2 * p + 0] = fmaf(wa, fa.x, fmaf(wb, fb.x, acc[2 * p + 0]));
                acc[2 * p + 1] = fmaf(wa, fa.y, fmaf(wb, fb.y, acc[2 * p + 1]));
            }
        }

        unsigned int oi = g_oidx[t];
        float4* o4 = reinterpret_cast<float4*>(out + (size_t)oi * RR);
        o4[0] = make_float4(acc[0], acc[1], acc[2], acc[3]);
        o4[1] = make_float4(acc[4], acc[5], acc[6], acc[7]);
    }
}

extern "C" void kernel_launch(void* const* d_in, const int* in_sizes, int n_in,
                              void* d_out, int out_size) {
    const float4* xyuv = (const float4*)d_in[0];
    const float* grid  = (const float*)d_in[1];
    const float* mn4   = (const float*)d_in[2];
    const float* mx4   = (const float*)d_in[3];
    float* out = (float*)d_out;

    int n = in_sizes[0] / 4;  // 1,048,576 points
    if (n > NCAP) n = NCAP;

    static cudaStream_t sA = nullptr;
    static cudaEvent_t evFork = nullptr;
    static cudaEvent_t evT[N_STRIPES];
    if (!sA) {
        cudaStreamCreateWithFlags(&sA, cudaStreamNonBlocking);
        cudaEventCreateWithFlags(&evFork, cudaEventDisableTiming);
        for (int s = 0; s < N_STRIPES; s++)
            cudaEventCreateWithFlags(&evT[s], cudaEventDisableTiming);
    }

    int pBlocks = (n + 255) / 256;

    // Fork: side stream runs the 8 transpose stripes back-to-back.
    cudaEventRecord(evFork, 0);
    cudaStreamWaitEvent(sA, evFork, 0);
    for (int s = 0; s < N_STRIPES; s++) {
        transpose_stripe_kernel<<<T_STRIPE_BLOCKS, 256, 0, sA>>>(grid, s);
        cudaEventRecord(evT[s], sA);
    }

    // Main stream: binning chain (overlaps transpose stripes).
    zero_kernel<<<NBINS / 1024, 1024>>>();
    hist_kernel<<<pBlocks, 256>>>(xyuv, mn4, mx4, n);
    scan_local_kernel<<<SCAN_BLOCKS, 1024>>>();
    scan_top_kernel<<<1, SCAN_BLOCKS>>>(n);
    scan_add_kernel<<<SCAN_BLOCKS, 1024>>>();
    scatter_kernel<<<pBlocks, 256>>>(xyuv, mn4, mx4, n);

    // Per-stripe gathers, each gated on its transpose stripe.
    for (int s = 0; s < N_STRIPES; s++) {
        cudaStreamWaitEvent(0, evT[s], 0);
        gather_stripe_kernel<<<GATHER_STRIPE_BLOCKS, 256>>>(mn4, mx4, out, s);
    }
}

// round 16
// speedup vs baseline: 1.1339x; 1.1262x over previous
#include <cuda_runtime.h>
#include <cuda_fp16.h>

// Grid4D quadrilinear sample (round-9 structure + byte/BW tuning):
//  1) vectorized transpose grid [R,X,Y,U,V] fp32 -> gridT [X,Y,U,V,R] fp16
//  2) bin points by [morton(u_hi,v_hi)][x][y][morton(u_mid,v_mid)] -> 65536 bins
//  3) persistent gather in bin order; streaming hints keep L2 for gridT

#define RR 8
#define XX 9
#define YY 9
#define UU 512
#define VV 512
#define NS (XX * YY * UU * VV)     // 21,233,664 spatial cells
#define STR_R (NS)

#define NBINS 65536
#define SCAN_BLOCKS 64
#define NCAP (1 << 20)
#define GATHER_BLOCKS 740          // 5 per SM
#define CHUNK 256

__device__ uint4 g_gridT[(size_t)NS];            // ~340 MB fp16 transposed grid
__device__ unsigned int g_binCnt[NBINS];
__device__ unsigned int g_binCursor[NBINS];
__device__ unsigned int g_blkSum[SCAN_BLOCKS];
__device__ unsigned int g_blkOff[SCAN_BLOCKS];
__device__ float4 g_pts[NCAP];                   // sorted coords (16 MB)
__device__ unsigned int g_oidx[NCAP];            // original index (4 MB)
__device__ unsigned int g_ticket;

__device__ __forceinline__ unsigned int h2_to_u32(__half2 v) {
    return *reinterpret_cast<unsigned int*>(&v);
}
__device__ __forceinline__ __half2 u32_to_h2(unsigned int v) {
    return *reinterpret_cast<__half2*>(&v);
}

// ---------------- phase 1: transpose, 4 cells per thread ----------------
__global__ void __launch_bounds__(256)
transpose_kernel(const float* __restrict__ grid) {
    int q = blockIdx.x * blockDim.x + threadIdx.x;   // quad-cell id
    if (q >= NS / 4) return;
    int s = q * 4;                                   // 4 consecutive v-cells

    float4 vals[RR];                                 // per r-plane: 4 v-values
#pragma unroll
    for (int r = 0; r < RR; r++)
        vals[r] = __ldg(reinterpret_cast<const float4*>(grid + r * STR_R + s));

#pragma unroll
    for (int j = 0; j < 4; j++) {
        float cj[RR];
#pragma unroll
        for (int r = 0; r < RR; r++)
            cj[r] = (j == 0) ? vals[r].x : (j == 1) ? vals[r].y
                  : (j == 2) ? vals[r].z : vals[r].w;
        uint4 packed;
        packed.x = h2_to_u32(__floats2half2_rn(cj[0], cj[1]));
        packed.y = h2_to_u32(__floats2half2_rn(cj[2], cj[3]));
        packed.z = h2_to_u32(__floats2half2_rn(cj[4], cj[5]));
        packed.w = h2_to_u32(__floats2half2_rn(cj[6], cj[7]));
        g_gridT[s + j] = packed;
    }
}

// ---------------- shared coordinate math ----------------
__device__ __forceinline__ void prep_dim(float c, float mn, float mx, int S,
                                         int& c0, int& dd, float& w0, float& w1) {
    float ind = (c - mn) / (mx - mn) * 2.0f - 1.0f;
    float pos = (ind + 1.0f) * 0.5f * (float)(S - 1);
    float fl = floorf(pos);
    int i0 = (int)fl;
    float f = pos - fl;
    w0 = 1.0f - f;
    w1 = f;
    if (i0 < 0 || i0 >= S) w0 = 0.0f;        // zero-padding semantics
    int i1 = i0 + 1;
    if (i1 < 0 || i1 >= S) w1 = 0.0f;
    int cc0 = min(max(i0, 0), S - 1);
    int cc1 = min(max(i1, 0), S - 1);
    c0 = cc0;
    dd = cc1 - cc0;                           // 0 or 1
}

__device__ __forceinline__ int base_idx(float c, float mn, float mx, int S) {
    float ind = (c - mn) / (mx - mn) * 2.0f - 1.0f;
    float pos = (ind + 1.0f) * 0.5f * (float)(S - 1);
    int i0 = (int)floorf(pos);
    return min(max(i0, 0), S - 1);
}

__device__ __forceinline__ int morton3(int a, int b) {  // a,b in [0,8) -> 6 bits
    return ((a & 1) << 0) | ((b & 1) << 1) |
           (((a >> 1) & 1) << 2) | (((b >> 1) & 1) << 3) |
           (((a >> 2) & 1) << 4) | (((b >> 2) & 1) << 5);
}

__device__ __forceinline__ int compute_bin(float4 c, const float* mn4, const float* mx4) {
    int x0 = min(base_idx(c.x, mn4[0], mx4[0], XX), 7);
    int y0 = min(base_idx(c.y, mn4[1], mx4[1], YY), 7);
    int u0 = base_idx(c.z, mn4[2], mx4[2], UU);
    int v0 = base_idx(c.w, mn4[3], mx4[3], VV);
    int hi  = morton3(u0 >> 6, v0 >> 6);                 // 6 bits
    int um = (u0 >> 4) & 3, vm = (v0 >> 4) & 3;
    int mid = (um & 1) | ((vm & 1) << 1) | ((um >> 1) << 2) | ((vm >> 1) << 3);  // 4 bits
    return (((((hi << 3) | x0) << 3) | y0) << 4) | mid;  // 16 bits
}

// ---------------- phase 2: binning ----------------
__global__ void __launch_bounds__(1024)
zero_kernel() {
    int b = blockIdx.x * blockDim.x + threadIdx.x;
    if (b < NBINS) g_binCnt[b] = 0;
    if (b == 0) g_ticket = 0;
}

__global__ void __launch_bounds__(256)
hist_kernel(const float4* __restrict__ xyuv,
            const float* __restrict__ mn4, const float* __restrict__ mx4, int n) {
    int i = blockIdx.x * blockDim.x + threadIdx.x;
    if (i < n) atomicAdd(&g_binCnt[compute_bin(xyuv[i], mn4, mx4)], 1u);
}

// stage 1: per-block exclusive scan of 1024 bins, emit block total
__global__ void __launch_bounds__(1024)
scan_local_kernel() {
    __shared__ unsigned int s[1024];
    int t = threadIdx.x;
    int b = blockIdx.x * 1024 + t;
    unsigned int v = g_binCnt[b];
    s[t] = v;
    __syncthreads();
    for (int off = 1; off < 1024; off <<= 1) {
        unsigned int x = (t >= off) ? s[t - off] : 0u;
        __syncthreads();
        s[t] += x;
        __syncthreads();
    }
    g_binCursor[b] = s[t] - v;   // exclusive
    if (t == 1023) g_blkSum[blockIdx.x] = s[t];
}

// stage 2: scan the 64 block totals
__global__ void __launch_bounds__(SCAN_BLOCKS)
scan_top_kernel() {
    __shared__ unsigned int s[SCAN_BLOCKS];
    int t = threadIdx.x;
    unsigned int v = g_blkSum[t];
    s[t] = v;
    __syncthreads();
    for (int off = 1; off < SCAN_BLOCKS; off <<= 1) {
        unsigned int x = (t >= off) ? s[t - off] : 0u;
        __syncthreads();
        s[t] += x;
        __syncthreads();
    }
    g_blkOff[t] = s[t] - v;      // exclusive
}

// stage 3: add block offsets
__global__ void __launch_bounds__(1024)
scan_add_kernel() {
    int b = blockIdx.x * 1024 + threadIdx.x;
    g_binCursor[b] += g_blkOff[blockIdx.x];
}

__global__ void __launch_bounds__(256)
scatter_kernel(const float4* __restrict__ xyuv,
               const float* __restrict__ mn4, const float* __restrict__ mx4, int n) {
    int i = blockIdx.x * blockDim.x + threadIdx.x;
    if (i >= n) return;
    float4 c = xyuv[i];
    int bin = compute_bin(c, mn4, mx4);
    unsigned int pos = atomicAdd(&g_binCursor[bin], 1u);
    g_pts[pos] = c;
    g_oidx[pos] = (unsigned int)i;
}

// ---------------- phase 3: persistent gather with ticket queue ----------------
__global__ void __launch_bounds__(256)
gather_kernel(const float* __restrict__ mn4,
              const float* __restrict__ mx4,
              float* __restrict__ out, int n) {
    __shared__ unsigned int s_chunk;
    int nChunks = (n + CHUNK - 1) / CHUNK;

    for (;;) {
        __syncthreads();
        if (threadIdx.x == 0) s_chunk = atomicAdd(&g_ticket, 1u);
        __syncthreads();
        unsigned int chunk = s_chunk;
        if (chunk >= (unsigned int)nChunks) return;

        int t = (int)chunk * CHUNK + threadIdx.x;
        if (t < n) {
            float4 c = __ldcs(&g_pts[t]);          // read-once: evict-first

            int x0, y0, u0, v0, dx, dy, du, dv;
            float wx0, wx1, wy0, wy1, wu0, wu1, wv0, wv1;
            prep_dim(c.x, mn4[0], mx4[0], XX, x0, dx, wx0, wx1);
            prep_dim(c.y, mn4[1], mx4[1], YY, y0, dy, wy0, wy1);
            prep_dim(c.z, mn4[2], mx4[2], UU, u0, du, wu0, wu1);
            prep_dim(c.w, mn4[3], mx4[3], VV, v0, dv, wv0, wv1);

            int sidx[8];
            float w[8];
#pragma unroll
            for (int k = 0; k < 8; k++) {
                int xa = (k >> 2) & 1;
                int ya = (k >> 1) & 1;
                int ua = k & 1;
                int xi = x0 + (xa ? dx : 0);
                int yi = y0 + (ya ? dy : 0);
                int ui = u0 + (ua ? du : 0);
                sidx[k] = ((xi * YY + yi) * UU + ui) * VV + v0;
                w[k] = (xa ? wx1 : wx0) * (ya ? wy1 : wy0) * (ua ? wu1 : wu0);
            }

            float acc[RR];
#pragma unroll
            for (int r = 0; r < RR; r++) acc[r] = 0.0f;

#pragma unroll 2
            for (int k = 0; k < 8; k++) {
                int s0 = sidx[k];
                uint4 A = g_gridT[s0];
                uint4 B = g_gridT[s0 + dv];
                float wa = w[k] * wv0;
                float wb = w[k] * wv1;
                const unsigned int* au = &A.x;
                const unsigned int* bu = &B.x;
#pragma unroll
                for (int p = 0; p < 4; p++) {
                    float2 fa = __half22float2(u32_to_h2(au[p]));
                    float2 fb = __half22float2(u32_to_h2(bu[p]));
                    acc[2 * p + 0] = fmaf(wa, fa.x, fmaf(wb, fb.x, acc[2 * p + 0]));
                    acc[2 * p + 1] = fmaf(wa, fa.y, fmaf(wb, fb.y, acc[2 * p + 1]));
                }
            }

            unsigned int oi = __ldcs(&g_oidx[t]);  // read-once: evict-first
            float4* o4 = reinterpret_cast<float4*>(out + (size_t)oi * RR);
            // streaming stores: don't let output evict hot gridT lines in L2
            __stcs(&o4[0], make_float4(acc[0], acc[1], acc[2], acc[3]));
            __stcs(&o4[1], make_float4(acc[4], acc[5], acc[6], acc[7]));
        }
    }
}

extern "C" void kernel_launch(void* const* d_in, const int* in_sizes, int n_in,
                              void* d_out, int out_size) {
    const float4* xyuv = (const float4*)d_in[0];
    const float* grid  = (const float*)d_in[1];
    const float* mn4   = (const float*)d_in[2];
    const float* mx4   = (const float*)d_in[3];
    float* out = (float*)d_out;

    int n = in_sizes[0] / 4;  // 1,048,576 points
    if (n > NCAP) n = NCAP;

    int tThreads = 256;
    int tBlocks = (NS / 4 + tThreads - 1) / tThreads;
    transpose_kernel<<<tBlocks, tThreads>>>(grid);

    int pBlocks = (n + 255) / 256;
    zero_kernel<<<NBINS / 1024, 1024>>>();
    hist_kernel<<<pBlocks, 256>>>(xyuv, mn4, mx4, n);
    scan_local_kernel<<<SCAN_BLOCKS, 1024>>>();
    scan_top_kernel<<<1, SCAN_BLOCKS>>>();
    scan_add_kernel<<<SCAN_BLOCKS, 1024>>>();
    scatter_kernel<<<pBlocks, 256>>>(xyuv, mn4, mx4, n);

    gather_kernel<<<GATHER_BLOCKS, 256>>>(mn4, mx4, out, n);
}